// round 1
// baseline (speedup 1.0000x reference)
#include <cuda_runtime.h>
#include <cstdint>

#define BATCH 2
#define SEQ   2048
#define DMODEL 1024
#define NHEAD 16
#define DK    64

// Scratch (allocation-free): head-split projections + merged attention output
__device__ float g_q[BATCH*NHEAD*SEQ*DK];
__device__ float g_k[BATCH*NHEAD*SEQ*DK];
__device__ float g_v[BATCH*NHEAD*SEQ*DK];
__device__ float g_attn[BATCH*SEQ*DMODEL];

// ---------- helpers ----------
__device__ __forceinline__ float tfr(float f) {
    unsigned u;
    asm("cvt.rna.tf32.f32 %0, %1;" : "=r"(u) : "f"(f));
    return __uint_as_float(u);
}
__device__ __forceinline__ float4 tf4(float4 v) {
    v.x = tfr(v.x); v.y = tfr(v.y); v.z = tfr(v.z); v.w = tfr(v.w);
    return v;
}
__device__ __forceinline__ void mma_tf32(float c[4],
    unsigned a0, unsigned a1, unsigned a2, unsigned a3,
    unsigned b0, unsigned b1) {
    asm volatile(
        "mma.sync.aligned.m16n8k8.row.col.f32.tf32.tf32.f32 "
        "{%0,%1,%2,%3},{%4,%5,%6,%7},{%8,%9},{%0,%1,%2,%3};"
        : "+f"(c[0]), "+f"(c[1]), "+f"(c[2]), "+f"(c[3])
        : "r"(a0), "r"(a1), "r"(a2), "r"(a3), "r"(b0), "r"(b1));
}

// ---------- projection GEMM: C = A @ W^T + bias ----------
// A [4096,1024] row-major, W [1024,1024] row-major ([N][K] == col-major B)
// mode 1: write head-split [b,h,s,d]; mode 0: flat [m,n]
#define GK_STRIDE 36
__global__ __launch_bounds__(256) void proj_gemm(
    const float* __restrict__ A, const float* __restrict__ W,
    const float* __restrict__ bias, float* __restrict__ C, int mode)
{
    __shared__ float As[128 * GK_STRIDE];
    __shared__ float Ws[128 * GK_STRIDE];
    const int tid = threadIdx.x, lane = tid & 31, w = tid >> 5;
    const int g = lane >> 2, t = lane & 3;
    const int wr = w >> 1, wc = w & 1;
    const int mbase = blockIdx.y * 128, nbase = blockIdx.x * 128;

    float c[2][8][4];
#pragma unroll
    for (int mt = 0; mt < 2; mt++)
#pragma unroll
        for (int nt = 0; nt < 8; nt++)
#pragma unroll
            for (int i = 0; i < 4; i++) c[mt][nt][i] = 0.f;

    for (int k0 = 0; k0 < 1024; k0 += 32) {
#pragma unroll
        for (int i = 0; i < 4; i++) {
            int f = tid + i * 256;
            int row = f >> 3, c4 = f & 7;
            float4 a = *(const float4*)(A + (size_t)(mbase + row) * 1024 + k0 + c4 * 4);
            float4 wv = *(const float4*)(W + (size_t)(nbase + row) * 1024 + k0 + c4 * 4);
            *(float4*)(As + row * GK_STRIDE + c4 * 4) = tf4(a);
            *(float4*)(Ws + row * GK_STRIDE + c4 * 4) = tf4(wv);
        }
        __syncthreads();
#pragma unroll
        for (int kk = 0; kk < 4; kk++) {
            unsigned a[2][4], b[8][2];
#pragma unroll
            for (int mt = 0; mt < 2; mt++) {
                const float* p = As + (wr * 32 + mt * 16 + g) * GK_STRIDE + kk * 8 + t;
                a[mt][0] = __float_as_uint(p[0]);
                a[mt][1] = __float_as_uint(p[8 * GK_STRIDE]);
                a[mt][2] = __float_as_uint(p[4]);
                a[mt][3] = __float_as_uint(p[8 * GK_STRIDE + 4]);
            }
#pragma unroll
            for (int nt = 0; nt < 8; nt++) {
                const float* p = Ws + (wc * 64 + nt * 8 + g) * GK_STRIDE + kk * 8 + t;
                b[nt][0] = __float_as_uint(p[0]);
                b[nt][1] = __float_as_uint(p[4]);
            }
#pragma unroll
            for (int mt = 0; mt < 2; mt++)
#pragma unroll
                for (int nt = 0; nt < 8; nt++)
                    mma_tf32(c[mt][nt], a[mt][0], a[mt][1], a[mt][2], a[mt][3],
                             b[nt][0], b[nt][1]);
        }
        __syncthreads();
    }
    // epilogue
#pragma unroll
    for (int mt = 0; mt < 2; mt++)
#pragma unroll
        for (int nt = 0; nt < 8; nt++) {
            int rg0 = mbase + wr * 32 + mt * 16 + g;
            int ng0 = nbase + wc * 64 + nt * 8 + 2 * t;
#pragma unroll
            for (int ci = 0; ci < 4; ci++) {
                int mg = rg0 + ((ci >> 1) << 3);
                int ng = ng0 + (ci & 1);
                float v = c[mt][nt][ci] + __ldg(bias + ng);
                size_t idx;
                if (mode) {
                    int b_ = mg >> 11, s = mg & 2047, h = ng >> 6, d = ng & 63;
                    idx = ((size_t)((b_ * NHEAD + h) * SEQ + s)) * DK + d;
                } else {
                    idx = (size_t)mg * DMODEL + ng;
                }
                C[idx] = v;
            }
        }
}

// ---------- flash attention (causal) ----------
// grid: (16 q-tiles, 32 b*h), 256 threads
// smem (floats): Qs[128*68] Ks[128*68] Vs[64*132 transposed] Ps[128*132]
//                ms[128] ls[128] al[128] red[256]
#define OFF_K   8704
#define OFF_V   17408
#define OFF_P   25856
#define OFF_M   42752
#define OFF_L   42880
#define OFF_A   43008
#define OFF_R   43136
#define ATTN_SMEM_BYTES (43392 * 4)

__global__ __launch_bounds__(256) void attn_kernel()
{
    extern __shared__ float sm[];
    float* Qs = sm;
    float* Ks = sm + OFF_K;
    float* Vs = sm + OFF_V;
    float* Ps = sm + OFF_P;
    float* ms = sm + OFF_M;
    float* ls = sm + OFF_L;
    float* al = sm + OFF_A;
    float* red = sm + OFF_R;

    const int qt = blockIdx.x;
    const int bh = blockIdx.y;
    const float* qp = g_q + (size_t)bh * SEQ * DK;
    const float* kp = g_k + (size_t)bh * SEQ * DK;
    const float* vp = g_v + (size_t)bh * SEQ * DK;

    const int tid = threadIdx.x, lane = tid & 31, w = tid >> 5;
    const int g = lane >> 2, t = lane & 3;
    const int wr = w >> 1, wc = w & 1;

    // load Q tile (tf32-rounded)
#pragma unroll
    for (int i = 0; i < 8; i++) {
        int f = tid + i * 256;
        int row = f >> 4, c4 = f & 15;
        float4 v = *(const float4*)(qp + (size_t)(qt * 128 + row) * DK + c4 * 4);
        *(float4*)(Qs + row * 68 + c4 * 4) = tf4(v);
    }
    if (tid < 128) { ms[tid] = -1e30f; ls[tid] = 0.f; }

    float o[2][4][4];
#pragma unroll
    for (int mt = 0; mt < 2; mt++)
#pragma unroll
        for (int nt = 0; nt < 4; nt++)
#pragma unroll
            for (int i = 0; i < 4; i++) o[mt][nt][i] = 0.f;
    __syncthreads();

    for (int kt = 0; kt <= qt; kt++) {
        // load K tile (row-major) and V tile (transposed [d][kv])
#pragma unroll
        for (int i = 0; i < 8; i++) {
            int f = tid + i * 256;
            {
                int row = f >> 4, c4 = f & 15;
                float4 v = *(const float4*)(kp + (size_t)(kt * 128 + row) * DK + c4 * 4);
                *(float4*)(Ks + row * 68 + c4 * 4) = tf4(v);
            }
            {
                int row = f & 127, c4 = f >> 7;
                float4 v = *(const float4*)(vp + (size_t)(kt * 128 + row) * DK + c4 * 4);
                Vs[(c4 * 4 + 0) * 132 + row] = tfr(v.x);
                Vs[(c4 * 4 + 1) * 132 + row] = tfr(v.y);
                Vs[(c4 * 4 + 2) * 132 + row] = tfr(v.z);
                Vs[(c4 * 4 + 3) * 132 + row] = tfr(v.w);
            }
        }
        __syncthreads();

        // S = Q @ K^T : warp = [32 q rows (wr)] x [64 kv cols (wc)]
        float s[2][8][4];
#pragma unroll
        for (int mt = 0; mt < 2; mt++)
#pragma unroll
            for (int nt = 0; nt < 8; nt++)
#pragma unroll
                for (int i = 0; i < 4; i++) s[mt][nt][i] = 0.f;
#pragma unroll
        for (int kk = 0; kk < 8; kk++) {
            unsigned a[2][4], b[8][2];
#pragma unroll
            for (int mt = 0; mt < 2; mt++) {
                const float* p = Qs + (wr * 32 + mt * 16 + g) * 68 + kk * 8 + t;
                a[mt][0] = __float_as_uint(p[0]);
                a[mt][1] = __float_as_uint(p[8 * 68]);
                a[mt][2] = __float_as_uint(p[4]);
                a[mt][3] = __float_as_uint(p[8 * 68 + 4]);
            }
#pragma unroll
            for (int nt = 0; nt < 8; nt++) {
                const float* p = Ks + (wc * 64 + nt * 8 + g) * 68 + kk * 8 + t;
                b[nt][0] = __float_as_uint(p[0]);
                b[nt][1] = __float_as_uint(p[4]);
            }
#pragma unroll
            for (int mt = 0; mt < 2; mt++)
#pragma unroll
                for (int nt = 0; nt < 8; nt++)
                    mma_tf32(s[mt][nt], a[mt][0], a[mt][1], a[mt][2], a[mt][3],
                             b[nt][0], b[nt][1]);
        }

        // scale + causal mask (only diagonal tile needs element mask)
        const bool diag = (kt == qt);
#pragma unroll
        for (int mt = 0; mt < 2; mt++)
#pragma unroll
            for (int nt = 0; nt < 8; nt++)
#pragma unroll
                for (int ci = 0; ci < 4; ci++) {
                    float v = s[mt][nt][ci] * 0.125f;
                    if (diag) {
                        int rl = wr * 32 + mt * 16 + g + ((ci >> 1) << 3);
                        int cl = wc * 64 + nt * 8 + 2 * t + (ci & 1);
                        if (cl > rl) v = -1e9f;
                    }
                    s[mt][nt][ci] = v;
                }

        // row max (per-thread -> quad -> cross-warp via smem)
        float rm[2][2];
#pragma unroll
        for (int mt = 0; mt < 2; mt++)
#pragma unroll
            for (int hh = 0; hh < 2; hh++) {
                float m = -1e30f;
#pragma unroll
                for (int nt = 0; nt < 8; nt++) {
                    m = fmaxf(m, s[mt][nt][hh * 2]);
                    m = fmaxf(m, s[mt][nt][hh * 2 + 1]);
                }
                m = fmaxf(m, __shfl_xor_sync(0xffffffffu, m, 1));
                m = fmaxf(m, __shfl_xor_sync(0xffffffffu, m, 2));
                rm[mt][hh] = m;
            }
        if (t == 0) {
#pragma unroll
            for (int mt = 0; mt < 2; mt++)
#pragma unroll
                for (int hh = 0; hh < 2; hh++)
                    red[wc * 128 + wr * 32 + mt * 16 + g + hh * 8] = rm[mt][hh];
        }
        __syncthreads();
        if (tid < 128) {
            float mo = ms[tid];
            float mn = fmaxf(mo, fmaxf(red[tid], red[128 + tid]));
            float a_ = __expf(mo - mn);
            ms[tid] = mn; al[tid] = a_; ls[tid] *= a_;
        }
        __syncthreads();

        // P = exp(S - m), stage into smem (tf32), partial row-sums, rescale O
        float rs[2][2] = {{0.f, 0.f}, {0.f, 0.f}};
#pragma unroll
        for (int mt = 0; mt < 2; mt++)
#pragma unroll
            for (int hh = 0; hh < 2; hh++) {
                int rl = wr * 32 + mt * 16 + g + hh * 8;
                float mn = ms[rl];
#pragma unroll
                for (int nt = 0; nt < 8; nt++)
#pragma unroll
                    for (int q = 0; q < 2; q++) {
                        float p = __expf(s[mt][nt][hh * 2 + q] - mn);
                        rs[mt][hh] += p;
                        Ps[rl * 132 + wc * 64 + nt * 8 + 2 * t + q] = tfr(p);
                    }
                float a_ = al[rl];
#pragma unroll
                for (int nt = 0; nt < 4; nt++)
#pragma unroll
                    for (int q = 0; q < 2; q++)
                        o[mt][nt][hh * 2 + q] *= a_;
            }
#pragma unroll
        for (int mt = 0; mt < 2; mt++)
#pragma unroll
            for (int hh = 0; hh < 2; hh++) {
                float v = rs[mt][hh];
                v += __shfl_xor_sync(0xffffffffu, v, 1);
                v += __shfl_xor_sync(0xffffffffu, v, 2);
                rs[mt][hh] = v;
            }
        if (t == 0) {
#pragma unroll
            for (int mt = 0; mt < 2; mt++)
#pragma unroll
                for (int hh = 0; hh < 2; hh++)
                    red[wc * 128 + wr * 32 + mt * 16 + g + hh * 8] = rs[mt][hh];
        }
        __syncthreads();
        if (tid < 128) ls[tid] += red[tid] + red[128 + tid];

        // O += P @ V : warp = [32 q rows (wr)] x [32 d cols (wc)]
#pragma unroll
        for (int kk = 0; kk < 16; kk++) {
            unsigned a[2][4], b[4][2];
#pragma unroll
            for (int mt = 0; mt < 2; mt++) {
                const float* p = Ps + (wr * 32 + mt * 16 + g) * 132 + kk * 8 + t;
                a[mt][0] = __float_as_uint(p[0]);
                a[mt][1] = __float_as_uint(p[8 * 132]);
                a[mt][2] = __float_as_uint(p[4]);
                a[mt][3] = __float_as_uint(p[8 * 132 + 4]);
            }
#pragma unroll
            for (int nt = 0; nt < 4; nt++) {
                const float* p = Vs + (wc * 32 + nt * 8 + g) * 132 + kk * 8 + t;
                b[nt][0] = __float_as_uint(p[0]);
                b[nt][1] = __float_as_uint(p[4]);
            }
#pragma unroll
            for (int mt = 0; mt < 2; mt++)
#pragma unroll
                for (int nt = 0; nt < 4; nt++)
                    mma_tf32(o[mt][nt], a[mt][0], a[mt][1], a[mt][2], a[mt][3],
                             b[nt][0], b[nt][1]);
        }
        __syncthreads();
    }

    // epilogue: O / l, merge heads -> g_attn [B,S,DMODEL]
    const int b_ = bh >> 4, h = bh & 15;
    float* outp = g_attn + ((size_t)b_ * SEQ + qt * 128) * DMODEL + h * DK;
#pragma unroll
    for (int mt = 0; mt < 2; mt++)
#pragma unroll
        for (int nt = 0; nt < 4; nt++)
#pragma unroll
            for (int ci = 0; ci < 4; ci++) {
                int rl = wr * 32 + mt * 16 + g + ((ci >> 1) << 3);
                int dl = wc * 32 + nt * 8 + 2 * t + (ci & 1);
                outp[(size_t)rl * DMODEL + dl] = o[mt][nt][ci] / ls[rl];
            }
}

// ---------- launch ----------
extern "C" void kernel_launch(void* const* d_in, const int* in_sizes, int n_in,
                              void* d_out, int out_size)
{
    const float* q  = (const float*)d_in[0];
    const float* k  = (const float*)d_in[1];
    const float* v  = (const float*)d_in[2];
    // d_in[3] = mask (int32, known causal tril) — handled analytically
    const float* wq = (const float*)d_in[4];
    const float* bq = (const float*)d_in[5];
    const float* wk = (const float*)d_in[6];
    const float* bk = (const float*)d_in[7];
    const float* wv = (const float*)d_in[8];
    const float* bv = (const float*)d_in[9];
    const float* wo = (const float*)d_in[10];
    const float* bo = (const float*)d_in[11];

    float *pq, *pk, *pv, *pa;
    cudaGetSymbolAddress((void**)&pq, g_q);
    cudaGetSymbolAddress((void**)&pk, g_k);
    cudaGetSymbolAddress((void**)&pv, g_v);
    cudaGetSymbolAddress((void**)&pa, g_attn);

    dim3 gg(8, 32);
    proj_gemm<<<gg, 256>>>(q, wq, bq, pq, 1);
    proj_gemm<<<gg, 256>>>(k, wk, bk, pk, 1);
    proj_gemm<<<gg, 256>>>(v, wv, bv, pv, 1);

    cudaFuncSetAttribute(attn_kernel,
                         cudaFuncAttributeMaxDynamicSharedMemorySize,
                         ATTN_SMEM_BYTES);
    attn_kernel<<<dim3(16, 32), 256, ATTN_SMEM_BYTES>>>();

    proj_gemm<<<gg, 256>>>(pa, wo, bo, (float*)d_out, 0);
}

// round 2
// speedup vs baseline: 1.1912x; 1.1912x over previous
#include <cuda_runtime.h>
#include <cstdint>

#define BATCH 2
#define SEQ   2048
#define DMODEL 1024
#define NHEAD 16
#define DK    64

// Scratch (allocation-free)
__device__ float g_q[BATCH*NHEAD*SEQ*DK];
__device__ float g_k[BATCH*NHEAD*SEQ*DK];
__device__ float g_v[BATCH*NHEAD*SEQ*DK];
__device__ float g_attn[BATCH*SEQ*DMODEL];

// ---------- helpers ----------
__device__ __forceinline__ float tfr(float f) {
    unsigned u;
    asm("cvt.rna.tf32.f32 %0, %1;" : "=r"(u) : "f"(f));
    return __uint_as_float(u);
}
__device__ __forceinline__ float4 tf4(float4 v) {
    v.x = tfr(v.x); v.y = tfr(v.y); v.z = tfr(v.z); v.w = tfr(v.w);
    return v;
}
__device__ __forceinline__ void mma_tf32(float c[4],
    unsigned a0, unsigned a1, unsigned a2, unsigned a3,
    unsigned b0, unsigned b1) {
    asm volatile(
        "mma.sync.aligned.m16n8k8.row.col.f32.tf32.tf32.f32 "
        "{%0,%1,%2,%3},{%4,%5,%6,%7},{%8,%9},{%0,%1,%2,%3};"
        : "+f"(c[0]), "+f"(c[1]), "+f"(c[2]), "+f"(c[3])
        : "r"(a0), "r"(a1), "r"(a2), "r"(a3), "r"(b0), "r"(b1));
}

// ---------- projection GEMM: C = A @ W^T + bias (reg-prefetch pipelined) ----------
// qkv=1: blockIdx.z selects {q,k,v}, writes head-split [b,h,s,d]
// qkv=0: single A/W, writes flat [m,n]
#define GK_STRIDE 36
__global__ __launch_bounds__(256) void proj_gemm(
    const float* __restrict__ A0, const float* __restrict__ W0,
    const float* __restrict__ B0, float* __restrict__ C0,
    const float* __restrict__ A1, const float* __restrict__ W1,
    const float* __restrict__ B1, float* __restrict__ C1,
    const float* __restrict__ A2, const float* __restrict__ W2,
    const float* __restrict__ B2, float* __restrict__ C2,
    int qkv)
{
    __shared__ float As[128 * GK_STRIDE];
    __shared__ float Ws[128 * GK_STRIDE];
    const float *A = A0, *W = W0, *bias = B0;
    float* C = C0;
    if (qkv) {
        if (blockIdx.z == 1) { A = A1; W = W1; bias = B1; C = C1; }
        else if (blockIdx.z == 2) { A = A2; W = W2; bias = B2; C = C2; }
    }
    const int tid = threadIdx.x, lane = tid & 31, w = tid >> 5;
    const int g = lane >> 2, t = lane & 3;
    const int wr = w >> 1, wc = w & 1;
    const int mbase = blockIdx.y * 128, nbase = blockIdx.x * 128;
    const int lrow = tid >> 3, lc4 = (tid & 7) * 4;

    float c[2][8][4];
#pragma unroll
    for (int mt = 0; mt < 2; mt++)
#pragma unroll
        for (int nt = 0; nt < 8; nt++)
#pragma unroll
            for (int i = 0; i < 4; i++) c[mt][nt][i] = 0.f;

    float4 ar[4], wr4[4];
    // prefetch k0 = 0
#pragma unroll
    for (int i = 0; i < 4; i++) {
        ar[i]  = *(const float4*)(A + (size_t)(mbase + lrow + i * 32) * 1024 + lc4);
        wr4[i] = *(const float4*)(W + (size_t)(nbase + lrow + i * 32) * 1024 + lc4);
    }

    for (int k0 = 0; k0 < 1024; k0 += 32) {
        // store current tile (tf32-rounded)
#pragma unroll
        for (int i = 0; i < 4; i++) {
            *(float4*)(As + (lrow + i * 32) * GK_STRIDE + lc4) = tf4(ar[i]);
            *(float4*)(Ws + (lrow + i * 32) * GK_STRIDE + lc4) = tf4(wr4[i]);
        }
        __syncthreads();
        // prefetch next tile
        if (k0 + 32 < 1024) {
#pragma unroll
            for (int i = 0; i < 4; i++) {
                ar[i]  = *(const float4*)(A + (size_t)(mbase + lrow + i * 32) * 1024 + k0 + 32 + lc4);
                wr4[i] = *(const float4*)(W + (size_t)(nbase + lrow + i * 32) * 1024 + k0 + 32 + lc4);
            }
        }
#pragma unroll
        for (int kk = 0; kk < 4; kk++) {
            unsigned a[2][4], b[8][2];
#pragma unroll
            for (int mt = 0; mt < 2; mt++) {
                const float* p = As + (wr * 32 + mt * 16 + g) * GK_STRIDE + kk * 8 + t;
                a[mt][0] = __float_as_uint(p[0]);
                a[mt][1] = __float_as_uint(p[8 * GK_STRIDE]);
                a[mt][2] = __float_as_uint(p[4]);
                a[mt][3] = __float_as_uint(p[8 * GK_STRIDE + 4]);
            }
#pragma unroll
            for (int nt = 0; nt < 8; nt++) {
                const float* p = Ws + (wc * 64 + nt * 8 + g) * GK_STRIDE + kk * 8 + t;
                b[nt][0] = __float_as_uint(p[0]);
                b[nt][1] = __float_as_uint(p[4]);
            }
#pragma unroll
            for (int mt = 0; mt < 2; mt++)
#pragma unroll
                for (int nt = 0; nt < 8; nt++)
                    mma_tf32(c[mt][nt], a[mt][0], a[mt][1], a[mt][2], a[mt][3],
                             b[nt][0], b[nt][1]);
        }
        __syncthreads();
    }
    // epilogue
#pragma unroll
    for (int mt = 0; mt < 2; mt++)
#pragma unroll
        for (int nt = 0; nt < 8; nt++) {
            int rg0 = mbase + wr * 32 + mt * 16 + g;
            int ng0 = nbase + wc * 64 + nt * 8 + 2 * t;
#pragma unroll
            for (int ci = 0; ci < 4; ci++) {
                int mg = rg0 + ((ci >> 1) << 3);
                int ng = ng0 + (ci & 1);
                float v = c[mt][nt][ci] + __ldg(bias + ng);
                size_t idx;
                if (qkv) {
                    int b_ = mg >> 11, s = mg & 2047, h = ng >> 6, d = ng & 63;
                    idx = ((size_t)((b_ * NHEAD + h) * SEQ + s)) * DK + d;
                } else {
                    idx = (size_t)mg * DMODEL + ng;
                }
                C[idx] = v;
            }
        }
}

// ---------- flash attention (causal, warp-local softmax, shuffle P-relayout) ----------
// grid: (16 q-tiles, 32 b*h), 256 threads (8 warps x 16 q-rows)
// KV tile = 64. smem: Qs[128*68] Ks[64*68] Vs[64*68 transposed]
#define AOFF_K 8704
#define AOFF_V 13056
#define ATTN_SMEM_BYTES (17408 * 4)

__global__ __launch_bounds__(256) void attn_kernel()
{
    extern __shared__ float sm[];
    float* Qs = sm;
    float* Ks = sm + AOFF_K;
    float* Vs = sm + AOFF_V;

    const int qt = blockIdx.x;
    const int bh = blockIdx.y;
    const int qbase = qt * 128;
    const float* qp = g_q + (size_t)bh * SEQ * DK;
    const float* kp = g_k + (size_t)bh * SEQ * DK;
    const float* vp = g_v + (size_t)bh * SEQ * DK;

    const int tid = threadIdx.x, lane = tid & 31, w = tid >> 5;
    const int g = lane >> 2, t = lane & 3;

    // ---- load Q tile (tf32) ----
#pragma unroll
    for (int i = 0; i < 8; i++) {
        int f = tid + i * 256;
        int row = f >> 4, c4 = (f & 15) * 4;
        float4 v = *(const float4*)(qp + (size_t)(qbase + row) * DK + c4);
        *(float4*)(Qs + row * 68 + c4) = tf4(v);
    }

    float m0 = -1e30f, m1 = -1e30f, l0 = 0.f, l1 = 0.f;
    float o[8][4];
#pragma unroll
    for (int nt = 0; nt < 8; nt++)
#pragma unroll
        for (int i = 0; i < 4; i++) o[nt][i] = 0.f;

    const int nkt = 2 * qt + 2;
    const int lrow = tid >> 4, lc4 = (tid & 15) * 4;

    // prefetch tile 0
    float4 kr[4], vr4[4];
#pragma unroll
    for (int i = 0; i < 4; i++) {
        kr[i]  = *(const float4*)(kp + (size_t)(lrow + i * 16) * DK + lc4);
        vr4[i] = *(const float4*)(vp + (size_t)(lrow + i * 16) * DK + lc4);
    }
    __syncthreads();

    for (int kt = 0; kt < nkt; kt++) {
        const int kb = kt * 64;
        // ---- store K (row-major) / V (transposed) tiles ----
#pragma unroll
        for (int i = 0; i < 4; i++) {
            int row = lrow + i * 16;
            *(float4*)(Ks + row * 68 + lc4) = tf4(kr[i]);
            Vs[(lc4 + 0) * 68 + row] = tfr(vr4[i].x);
            Vs[(lc4 + 1) * 68 + row] = tfr(vr4[i].y);
            Vs[(lc4 + 2) * 68 + row] = tfr(vr4[i].z);
            Vs[(lc4 + 3) * 68 + row] = tfr(vr4[i].w);
        }
        __syncthreads();
        // prefetch next tile
        if (kt + 1 < nkt) {
            const float* kpn = kp + (size_t)(kb + 64) * DK;
            const float* vpn = vp + (size_t)(kb + 64) * DK;
#pragma unroll
            for (int i = 0; i < 4; i++) {
                kr[i]  = *(const float4*)(kpn + (size_t)(lrow + i * 16) * DK + lc4);
                vr4[i] = *(const float4*)(vpn + (size_t)(lrow + i * 16) * DK + lc4);
            }
        }

        // ---- S = Q @ K^T : warp owns 16 q-rows x 64 kv ----
        float s[8][4];
#pragma unroll
        for (int nt = 0; nt < 8; nt++)
#pragma unroll
            for (int i = 0; i < 4; i++) s[nt][i] = 0.f;
#pragma unroll
        for (int kk = 0; kk < 8; kk++) {
            const float* ap = Qs + (w * 16 + g) * 68 + kk * 8 + t;
            unsigned a0 = __float_as_uint(ap[0]);
            unsigned a1 = __float_as_uint(ap[8 * 68]);
            unsigned a2 = __float_as_uint(ap[4]);
            unsigned a3 = __float_as_uint(ap[8 * 68 + 4]);
#pragma unroll
            for (int nt = 0; nt < 8; nt++) {
                const float* bp = Ks + (nt * 8 + g) * 68 + kk * 8 + t;
                mma_tf32(s[nt], a0, a1, a2, a3,
                         __float_as_uint(bp[0]), __float_as_uint(bp[4]));
            }
        }

        // ---- scale + causal mask ----
        const bool masked = (kb + 64 > qbase);
        const int r0 = qbase + w * 16 + g, r1 = r0 + 8;
#pragma unroll
        for (int nt = 0; nt < 8; nt++) {
            int cg = kb + nt * 8 + 2 * t;
            s[nt][0] *= 0.125f; s[nt][1] *= 0.125f;
            s[nt][2] *= 0.125f; s[nt][3] *= 0.125f;
            if (masked) {
                if (cg     > r0) s[nt][0] = -1e9f;
                if (cg + 1 > r0) s[nt][1] = -1e9f;
                if (cg     > r1) s[nt][2] = -1e9f;
                if (cg + 1 > r1) s[nt][3] = -1e9f;
            }
        }

        // ---- warp-local online softmax (rows r0 / r1) ----
        float mc0 = -1e30f, mc1 = -1e30f;
#pragma unroll
        for (int nt = 0; nt < 8; nt++) {
            mc0 = fmaxf(mc0, fmaxf(s[nt][0], s[nt][1]));
            mc1 = fmaxf(mc1, fmaxf(s[nt][2], s[nt][3]));
        }
        mc0 = fmaxf(mc0, __shfl_xor_sync(0xffffffffu, mc0, 1));
        mc0 = fmaxf(mc0, __shfl_xor_sync(0xffffffffu, mc0, 2));
        mc1 = fmaxf(mc1, __shfl_xor_sync(0xffffffffu, mc1, 1));
        mc1 = fmaxf(mc1, __shfl_xor_sync(0xffffffffu, mc1, 2));
        float mn0 = fmaxf(m0, mc0), mn1 = fmaxf(m1, mc1);
        float al0 = __expf(m0 - mn0), al1 = __expf(m1 - mn1);
        m0 = mn0; m1 = mn1;
        l0 *= al0; l1 *= al1;
        float rs0 = 0.f, rs1 = 0.f;
#pragma unroll
        for (int nt = 0; nt < 8; nt++) {
            float p0 = __expf(s[nt][0] - mn0);
            float p1 = __expf(s[nt][1] - mn0);
            float p2 = __expf(s[nt][2] - mn1);
            float p3 = __expf(s[nt][3] - mn1);
            rs0 += p0 + p1; rs1 += p2 + p3;
            s[nt][0] = tfr(p0); s[nt][1] = tfr(p1);
            s[nt][2] = tfr(p2); s[nt][3] = tfr(p3);
            o[nt][0] *= al0; o[nt][1] *= al0;
            o[nt][2] *= al1; o[nt][3] *= al1;
        }
        rs0 += __shfl_xor_sync(0xffffffffu, rs0, 1);
        rs0 += __shfl_xor_sync(0xffffffffu, rs0, 2);
        rs1 += __shfl_xor_sync(0xffffffffu, rs1, 1);
        rs1 += __shfl_xor_sync(0xffffffffu, rs1, 2);
        l0 += rs0; l1 += rs1;

        // ---- O += P @ V (P relayout via warp shuffles) ----
        const int L0 = g * 4 + (t >> 1);
        const int L1 = L0 + 2;
        const bool sel = t & 1;
#pragma unroll
        for (int kk = 0; kk < 8; kk++) {
            float x0 = __shfl_sync(0xffffffffu, s[kk][0], L0);
            float x1 = __shfl_sync(0xffffffffu, s[kk][1], L0);
            float x2 = __shfl_sync(0xffffffffu, s[kk][2], L0);
            float x3 = __shfl_sync(0xffffffffu, s[kk][3], L0);
            float y0 = __shfl_sync(0xffffffffu, s[kk][0], L1);
            float y1 = __shfl_sync(0xffffffffu, s[kk][1], L1);
            float y2 = __shfl_sync(0xffffffffu, s[kk][2], L1);
            float y3 = __shfl_sync(0xffffffffu, s[kk][3], L1);
            unsigned a0 = __float_as_uint(sel ? x1 : x0);
            unsigned a1 = __float_as_uint(sel ? x3 : x2);
            unsigned a2 = __float_as_uint(sel ? y1 : y0);
            unsigned a3 = __float_as_uint(sel ? y3 : y2);
#pragma unroll
            for (int nt = 0; nt < 8; nt++) {
                const float* bp = Vs + (nt * 8 + g) * 68 + kk * 8 + t;
                mma_tf32(o[nt], a0, a1, a2, a3,
                         __float_as_uint(bp[0]), __float_as_uint(bp[4]));
            }
        }
        __syncthreads();
    }

    // ---- epilogue: O/l, merge heads -> g_attn [B,S,DMODEL] ----
    const int b_ = bh >> 4, h = bh & 15;
    const float il0 = 1.f / l0, il1 = 1.f / l1;
    float* outp = g_attn + ((size_t)b_ * SEQ + qbase) * DMODEL + h * DK;
    const int rl0 = w * 16 + g;
#pragma unroll
    for (int nt = 0; nt < 8; nt++) {
        int dl = nt * 8 + 2 * t;
        outp[(size_t)rl0 * DMODEL + dl]           = o[nt][0] * il0;
        outp[(size_t)rl0 * DMODEL + dl + 1]       = o[nt][1] * il0;
        outp[(size_t)(rl0 + 8) * DMODEL + dl]     = o[nt][2] * il1;
        outp[(size_t)(rl0 + 8) * DMODEL + dl + 1] = o[nt][3] * il1;
    }
}

// ---------- launch ----------
extern "C" void kernel_launch(void* const* d_in, const int* in_sizes, int n_in,
                              void* d_out, int out_size)
{
    const float* q  = (const float*)d_in[0];
    const float* k  = (const float*)d_in[1];
    const float* v  = (const float*)d_in[2];
    const float* wq = (const float*)d_in[4];
    const float* bq = (const float*)d_in[5];
    const float* wk = (const float*)d_in[6];
    const float* bk = (const float*)d_in[7];
    const float* wv = (const float*)d_in[8];
    const float* bv = (const float*)d_in[9];
    const float* wo = (const float*)d_in[10];
    const float* bo = (const float*)d_in[11];

    float *pq, *pk, *pv, *pa;
    cudaGetSymbolAddress((void**)&pq, g_q);
    cudaGetSymbolAddress((void**)&pk, g_k);
    cudaGetSymbolAddress((void**)&pv, g_v);
    cudaGetSymbolAddress((void**)&pa, g_attn);

    // fused Q/K/V projections (z selects which)
    proj_gemm<<<dim3(8, 32, 3), 256>>>(q, wq, bq, pq,
                                       k, wk, bk, pk,
                                       v, wv, bv, pv, 1);

    cudaFuncSetAttribute(attn_kernel,
                         cudaFuncAttributeMaxDynamicSharedMemorySize,
                         ATTN_SMEM_BYTES);
    attn_kernel<<<dim3(16, 32), 256, ATTN_SMEM_BYTES>>>();

    proj_gemm<<<dim3(8, 32, 1), 256>>>(pa, wo, bo, (float*)d_out,
                                       nullptr, nullptr, nullptr, nullptr,
                                       nullptr, nullptr, nullptr, nullptr, 0);
}